// round 10
// baseline (speedup 1.0000x reference)
#include <cuda_runtime.h>
#include <cuda_bf16.h>
#include <cstdint>

#define D_DIM    256
#define NBC      10
#define MAX_M    1024
#define MAX_N    100000
#define MAX_NP   100096
#define CAP      2048
#define MARGIN   0.03f
#define KC       64
#define ASTRIDE  72      // bf16 elems per smem row (64 + 8 pad)

#define STAGE_BYTES 36864          // A chunk (18432) + B chunk (18432)
#define SM_NX    (2 * STAGE_BYTES) // 73728
#define SMEM_BYTES (SM_NX + 512)   // 74240  -> 3 CTAs/SM

__device__ float              g_xq[MAX_M * D_DIM];
__device__ unsigned short     g_qb[MAX_M * D_DIM];
__device__ unsigned short     g_Xb[(size_t)MAX_NP * D_DIM];   // pad rows stay 0
__device__ float              g_nx2[MAX_N];
__device__ unsigned long long g_min[MAX_M];
__device__ int                g_cnum[MAX_M];
__device__ int                g_cand[MAX_M * CAP];

__device__ __forceinline__ unsigned f2ord(float f) {
    unsigned u = __float_as_uint(f);
    return (u & 0x80000000u) ? ~u : (u | 0x80000000u);
}
__device__ __forceinline__ float ord2f(unsigned o) {
    return __uint_as_float((o & 0x80000000u) ? (o ^ 0x80000000u) : ~o);
}
__device__ __forceinline__ unsigned smem_u32(const void* p) {
    unsigned a;
    asm("{ .reg .u64 t; cvta.to.shared.u64 t, %1; cvt.u32.u64 %0, t; }" : "=r"(a) : "l"(p));
    return a;
}
__device__ __forceinline__ void cp16(unsigned dst, const void* src) {
    asm volatile("cp.async.cg.shared.global [%0], [%1], 16;" :: "r"(dst), "l"(src));
}
#define CP_COMMIT() asm volatile("cp.async.commit_group;" ::: "memory")
#define CP_WAIT(n)  asm volatile("cp.async.wait_group %0;" :: "n"(n) : "memory")

__device__ __forceinline__ void ldsm_x4(unsigned& r0, unsigned& r1, unsigned& r2, unsigned& r3, unsigned addr) {
    asm volatile("ldmatrix.sync.aligned.m8n8.x4.shared.b16 {%0,%1,%2,%3}, [%4];"
        : "=r"(r0), "=r"(r1), "=r"(r2), "=r"(r3) : "r"(addr));
}
__device__ __forceinline__ void mma16816(float* c, const unsigned* a, unsigned b0, unsigned b1) {
    asm volatile(
        "mma.sync.aligned.m16n8k16.row.col.f32.bf16.bf16.f32 "
        "{%0,%1,%2,%3}, {%4,%5,%6,%7}, {%8,%9}, {%0,%1,%2,%3};"
        : "+f"(c[0]), "+f"(c[1]), "+f"(c[2]), "+f"(c[3])
        : "r"(a[0]), "r"(a[1]), "r"(a[2]), "r"(a[3]), "r"(b0), "r"(b1));
}

// ---------------------------------------------------------------------------
__global__ void prep_kernel(const float* __restrict__ x,
                            const float* __restrict__ center, int M) {
    int b = blockIdx.x, t = threadIdx.x;
    float v = x[b * D_DIM + t];
    float s = v * v;
    __shared__ float red[8];
    #pragma unroll
    for (int o = 16; o > 0; o >>= 1) s += __shfl_xor_sync(0xffffffffu, s, o);
    if ((t & 31) == 0) red[t >> 5] = s;
    __syncthreads();
    if (t < 8) {
        float r = red[t];
        #pragma unroll
        for (int o = 4; o > 0; o >>= 1) r += __shfl_xor_sync(0xffu, r, o);
        if (t == 0) red[0] = r;
    }
    __syncthreads();
    float val = v / sqrtf(red[0]) - center[t];
    g_xq[b * D_DIM + t] = val;
    g_qb[b * D_DIM + t] = __bfloat16_as_ushort(__float2bfloat16(val));
}

__global__ void convert_kernel(const float* __restrict__ X, int N) {
    int w = (blockIdx.x * blockDim.x + threadIdx.x) >> 5;
    int lane = threadIdx.x & 31;
    if (w >= N) return;
    const float4* row = (const float4*)(X + (size_t)w * D_DIM);
    float4 v0 = row[lane * 2], v1 = row[lane * 2 + 1];
    float s = v0.x*v0.x + v0.y*v0.y + v0.z*v0.z + v0.w*v0.w
            + v1.x*v1.x + v1.y*v1.y + v1.z*v1.z + v1.w*v1.w;
    #pragma unroll
    for (int o = 16; o > 0; o >>= 1) s += __shfl_xor_sync(0xffffffffu, s, o);
    if (lane == 0) g_nx2[w] = s;
    uint4 o4;
    o4.x = __bfloat16_as_ushort(__float2bfloat16(v0.x)) | ((unsigned)__bfloat16_as_ushort(__float2bfloat16(v0.y)) << 16);
    o4.y = __bfloat16_as_ushort(__float2bfloat16(v0.z)) | ((unsigned)__bfloat16_as_ushort(__float2bfloat16(v0.w)) << 16);
    o4.z = __bfloat16_as_ushort(__float2bfloat16(v1.x)) | ((unsigned)__bfloat16_as_ushort(__float2bfloat16(v1.y)) << 16);
    o4.w = __bfloat16_as_ushort(__float2bfloat16(v1.z)) | ((unsigned)__bfloat16_as_ushort(__float2bfloat16(v1.w)) << 16);
    ((uint4*)(g_Xb + (size_t)w * D_DIM))[lane] = o4;
}

__global__ void init_kernel(int M) {
    int i = blockIdx.x * blockDim.x + threadIdx.x;
    if (i < M) { g_min[i] = ~0ull; g_cnum[i] = 0; }
}

// ---------------------------------------------------------------------------
// bf16 mma.sync GEMM (128x128x256), 2-stage cp.async, 3 CTAs/SM,
// reg-resident argmin/margin epilogue
// ---------------------------------------------------------------------------
__device__ __forceinline__ void load_chunk(unsigned stage, int m0, int n0,
                                           int kc, int tid) {
    #pragma unroll
    for (int r = 0; r < 4; r++) {
        int idx = tid + 256 * r;
        int row = idx >> 3, g = idx & 7;
        cp16(stage + (row * ASTRIDE + g * 8) * 2,
             g_qb + (size_t)(m0 + row) * D_DIM + kc + g * 8);
        cp16(stage + 18432 + (row * ASTRIDE + g * 8) * 2,
             g_Xb + (size_t)(n0 + row) * D_DIM + kc + g * 8);
    }
}

__global__ __launch_bounds__(256, 3)
void gemm_kernel(int N, int M) {
    extern __shared__ char sm[];
    float* nxs = (float*)(sm + SM_NX);
    unsigned smu = smem_u32(sm);

    int tid = threadIdx.x;
    int w = tid >> 5, lane = tid & 31;
    int wm = w >> 1, wn = w & 1;   // warp tile m32 x n64
    int m0 = blockIdx.x * 128;
    int n0 = blockIdx.y * 128;

    if (tid < 128) {
        int gn = n0 + tid;
        nxs[tid] = (gn < N) ? g_nx2[gn] : 1e30f;
    }

    float c[2][8][4];
    #pragma unroll
    for (int mi = 0; mi < 2; mi++)
        #pragma unroll
        for (int ni = 0; ni < 8; ni++)
            #pragma unroll
            for (int e = 0; e < 4; e++) c[mi][ni][e] = 0.f;

    // hoisted lane-dependent ldmatrix byte offsets (within a stage)
    unsigned aoff = (unsigned)(((wm * 32 + (lane & 15)) * ASTRIDE + (lane >> 4) * 8) * 2);
    unsigned boff = (unsigned)(18432 +
        ((wn * 64 + ((lane >> 4) & 1) * 8 + (lane & 7)) * ASTRIDE + ((lane >> 3) & 1) * 8) * 2);

    load_chunk(smu, m0, n0, 0, tid);
    CP_COMMIT();

    #pragma unroll
    for (int kc = 0; kc < 4; kc++) {
        int buf = kc & 1;
        if (kc < 3) {
            load_chunk(smu + (buf ^ 1) * STAGE_BYTES, m0, n0, (kc + 1) * KC, tid);
            CP_COMMIT();
            CP_WAIT(1);
        } else {
            CP_WAIT(0);
        }
        __syncthreads();

        unsigned stage = smu + buf * STAGE_BYTES;
        unsigned Au = stage + aoff;
        unsigned Bu = stage + boff;
        #pragma unroll
        for (int ks = 0; ks < 4; ks++) {
            unsigned a[2][4];
            #pragma unroll
            for (int mi = 0; mi < 2; mi++)
                ldsm_x4(a[mi][0], a[mi][1], a[mi][2], a[mi][3],
                        Au + mi * (16 * ASTRIDE * 2) + ks * 32);
            unsigned b[4][4];
            #pragma unroll
            for (int p = 0; p < 4; p++)
                ldsm_x4(b[p][0], b[p][1], b[p][2], b[p][3],
                        Bu + p * (16 * ASTRIDE * 2) + ks * 32);
            #pragma unroll
            for (int mi = 0; mi < 2; mi++)
                #pragma unroll
                for (int p = 0; p < 4; p++) {
                    mma16816(c[mi][2 * p + 0], a[mi], b[p][0], b[p][1]);
                    mma16816(c[mi][2 * p + 1], a[mi], b[p][2], b[p][3]);
                }
        }
        __syncthreads();   // reads of `stage` done before next iter overwrites it
    }

    // ---- register epilogue: per-row argmin + margin candidates ----
    int r = lane >> 2, qp = lane & 3;
    #pragma unroll
    for (int mi = 0; mi < 2; mi++) {
        #pragma unroll
        for (int h = 0; h < 2; h++) {
            int lrow = wm * 32 + mi * 16 + h * 8 + r;
            int q = m0 + lrow;
            unsigned long long kmin = ~0ull;
            #pragma unroll
            for (int ni = 0; ni < 8; ni++) {
                int lc = wn * 64 + ni * 8 + 2 * qp;
                float s0 = fmaf(-2.f, c[mi][ni][h * 2 + 0], nxs[lc]);
                float s1 = fmaf(-2.f, c[mi][ni][h * 2 + 1], nxs[lc + 1]);
                unsigned long long k0 = ((unsigned long long)f2ord(s0) << 32) | (unsigned)(n0 + lc);
                unsigned long long k1 = ((unsigned long long)f2ord(s1) << 32) | (unsigned)(n0 + lc + 1);
                if (k0 < kmin) kmin = k0;
                if (k1 < kmin) kmin = k1;
            }
            unsigned long long o1 = __shfl_xor_sync(0xffffffffu, kmin, 1);
            if (o1 < kmin) kmin = o1;
            unsigned long long o2 = __shfl_xor_sync(0xffffffffu, kmin, 2);
            if (o2 < kmin) kmin = o2;

            float thr = 0.f;
            if (qp == 0 && q < M) {
                unsigned long long old = atomicMin(&g_min[q], kmin);
                unsigned long long cur = (old < kmin) ? old : kmin;
                thr = ord2f((unsigned)(cur >> 32)) + MARGIN;
            }
            thr = __shfl_sync(0xffffffffu, thr, lane & ~3);

            if (q < M) {
                #pragma unroll
                for (int ni = 0; ni < 8; ni++) {
                    int lc = wn * 64 + ni * 8 + 2 * qp;
                    float s0 = fmaf(-2.f, c[mi][ni][h * 2 + 0], nxs[lc]);
                    float s1 = fmaf(-2.f, c[mi][ni][h * 2 + 1], nxs[lc + 1]);
                    if (s0 < thr) {
                        int p = atomicAdd(&g_cnum[q], 1);
                        if (p < CAP) g_cand[q * CAP + p] = n0 + lc;
                    }
                    if (s1 < thr) {
                        int p = atomicAdd(&g_cnum[q], 1);
                        if (p < CAP) g_cand[q * CAP + p] = n0 + lc + 1;
                    }
                }
            }
        }
    }
}

// ---------------------------------------------------------------------------
__global__ void rescore_kernel(const float* __restrict__ X) {
    __shared__ float xq[D_DIM];
    __shared__ unsigned long long wmin[8];
    int q = blockIdx.x;
    int tid = threadIdx.x, w = tid >> 5, lane = tid & 31;
    xq[tid] = g_xq[q * D_DIM + tid];
    int cnum = min(g_cnum[q], CAP);
    __syncthreads();
    unsigned long long key = ~0ull;
    for (int c = w; c < cnum; c += 8) {
        int gn = g_cand[q * CAP + c];
        const float4* row = (const float4*)(X + (size_t)gn * D_DIM);
        const float4* xv = (const float4*)xq;
        float4 v0 = row[lane * 2], v1 = row[lane * 2 + 1];
        float4 a0 = xv[lane * 2], a1 = xv[lane * 2 + 1];
        float dp = v0.x*a0.x + v0.y*a0.y + v0.z*a0.z + v0.w*a0.w
                 + v1.x*a1.x + v1.y*a1.y + v1.z*a1.z + v1.w*a1.w;
        #pragma unroll
        for (int o = 16; o > 0; o >>= 1) dp += __shfl_xor_sync(0xffffffffu, dp, o);
        float s = g_nx2[gn] - 2.f * dp;
        unsigned long long k = ((unsigned long long)f2ord(s) << 32) | (unsigned)gn;
        if (k < key) key = k;
    }
    if (lane == 0) wmin[w] = key;
    __syncthreads();
    if (tid == 0) {
        unsigned long long best = wmin[0];
        #pragma unroll
        for (int i = 1; i < 8; i++) if (wmin[i] < best) best = wmin[i];
        g_min[q] = best;
    }
}

// ---------------------------------------------------------------------------
__global__ void finalize_kernel(const int* __restrict__ labels,
                                const int* __restrict__ tni,
                                const int* __restrict__ cali,
                                float* __restrict__ out,
                                int M, int ncali, int Kn) {
    __shared__ int scali[1024];
    __shared__ int wcnt[8][NBC];
    for (int i = threadIdx.x; i < ncali; i += blockDim.x) scali[i] = cali[i];
    int w = threadIdx.x >> 5, lane = threadIdx.x & 31;
    if (lane < NBC) wcnt[w][lane] = 0;
    __syncthreads();
    int b = blockIdx.x * 8 + w;
    if (b < M) {
        int closest = (int)(g_min[b] & 0xffffffffull);
        for (int e = lane; e < Kn; e += 32) {
            int idx = (e == 0) ? closest : tni[(size_t)closest * (Kn - 1) + (e - 1)];
            atomicAdd(&wcnt[w][labels[idx]], 1);
        }
        __syncwarp();
        int key = 0x7fffffff;
        if (lane < NBC) {
            int v = Kn - wcnt[w][lane];
            int lo = 0, hi = ncali;
            while (lo < hi) {
                int mid = (lo + hi) >> 1;
                if (scali[mid] < v) lo = mid + 1; else hi = mid;
            }
            key = lo * 16 + lane;
        }
        #pragma unroll
        for (int o = 16; o > 0; o >>= 1)
            key = min(key, __shfl_xor_sync(0xffffffffu, key, o));
        if (lane == 0) {
            int pred = key & 15, pos = key >> 4;
            float pmax = (float)(ncali - pos) / (float)ncali;
            #pragma unroll
            for (int c = 0; c < NBC; c++)
                out[b * NBC + c] = (c == pred) ? pmax : 0.f;
        }
    }
}

// ---------------------------------------------------------------------------
extern "C" void kernel_launch(void* const* d_in, const int* in_sizes, int n_in,
                              void* d_out, int out_size) {
    const float* x      = (const float*)d_in[0];
    const float* X      = (const float*)d_in[1];
    const float* center = (const float*)d_in[2];
    const int*   labels = (const int*)d_in[3];
    const int*   tni    = (const int*)d_in[4];
    const int*   cali   = (const int*)d_in[5];
    float*       out    = (float*)d_out;

    int d     = in_sizes[2];
    int M     = in_sizes[0] / d;
    int N     = in_sizes[3];
    int ncali = in_sizes[5];
    int Kn    = in_sizes[4] / N + 1;

    cudaFuncSetAttribute(gemm_kernel, cudaFuncAttributeMaxDynamicSharedMemorySize, SMEM_BYTES);

    prep_kernel<<<M, 256>>>(x, center, M);
    convert_kernel<<<(N + 7) / 8, 256>>>(X, N);
    init_kernel<<<(M + 255) / 256, 256>>>(M);

    dim3 grid((M + 127) / 128, (N + 127) / 128);
    gemm_kernel<<<grid, 256, SMEM_BYTES>>>(N, M);

    rescore_kernel<<<M, 256>>>(X);
    finalize_kernel<<<(M + 7) / 8, 256>>>(labels, tni, cali, out, M, ncali, Kn);
}

// round 11
// speedup vs baseline: 1.7710x; 1.7710x over previous
#include <cuda_runtime.h>
#include <cuda_fp16.h>
#include <cstdint>

#define D_DIM    256
#define NBC      10
#define MAX_M    1024
#define MAX_N    100000
#define MAX_NP   100096
#define CAP      2048
#define MARGIN   0.08f
#define KC       64
#define ASTRIDE  72      // fp16 elems per smem row (64 + 8 pad)

#define STAGE_BYTES 36864          // A chunk (18432) + B chunk (18432)
#define SM_NX    (2 * STAGE_BYTES) // 73728
#define SMEM_BYTES (SM_NX + 512)   // 74240

__device__ float              g_xq[MAX_M * D_DIM];
__device__ unsigned short     g_qb[MAX_M * D_DIM];          // fp16 bits
__device__ unsigned short     g_Xb[(size_t)MAX_NP * D_DIM]; // fp16 bits, pad rows 0
__device__ float              g_nx2[MAX_N];
__device__ unsigned long long g_min[MAX_M];
__device__ int                g_cnum[MAX_M];
__device__ int                g_cand[MAX_M * CAP];

__device__ __forceinline__ unsigned f2ord(float f) {
    unsigned u = __float_as_uint(f);
    return (u & 0x80000000u) ? ~u : (u | 0x80000000u);
}
__device__ __forceinline__ float ord2f(unsigned o) {
    return __uint_as_float((o & 0x80000000u) ? (o ^ 0x80000000u) : ~o);
}
__device__ __forceinline__ unsigned smem_u32(const void* p) {
    unsigned a;
    asm("{ .reg .u64 t; cvta.to.shared.u64 t, %1; cvt.u32.u64 %0, t; }" : "=r"(a) : "l"(p));
    return a;
}
__device__ __forceinline__ void cp16(unsigned dst, const void* src) {
    asm volatile("cp.async.cg.shared.global [%0], [%1], 16;" :: "r"(dst), "l"(src));
}
#define CP_COMMIT() asm volatile("cp.async.commit_group;" ::: "memory")
#define CP_WAIT(n)  asm volatile("cp.async.wait_group %0;" :: "n"(n) : "memory")

__device__ __forceinline__ void ldsm_x4(unsigned& r0, unsigned& r1, unsigned& r2, unsigned& r3, unsigned addr) {
    asm volatile("ldmatrix.sync.aligned.m8n8.x4.shared.b16 {%0,%1,%2,%3}, [%4];"
        : "=r"(r0), "=r"(r1), "=r"(r2), "=r"(r3) : "r"(addr));
}
// fp16 accumulate: 2 c-regs (4 halves) per fragment
__device__ __forceinline__ void mma16816h(unsigned* c, const unsigned* a, unsigned b0, unsigned b1) {
    asm volatile(
        "mma.sync.aligned.m16n8k16.row.col.f16.f16.f16.f16 "
        "{%0,%1}, {%2,%3,%4,%5}, {%6,%7}, {%0,%1};"
        : "+r"(c[0]), "+r"(c[1])
        : "r"(a[0]), "r"(a[1]), "r"(a[2]), "r"(a[3]), "r"(b0), "r"(b1));
}

// ---------------------------------------------------------------------------
__global__ void prep_kernel(const float* __restrict__ x,
                            const float* __restrict__ center, int M) {
    int b = blockIdx.x, t = threadIdx.x;
    float v = x[b * D_DIM + t];
    float s = v * v;
    __shared__ float red[8];
    #pragma unroll
    for (int o = 16; o > 0; o >>= 1) s += __shfl_xor_sync(0xffffffffu, s, o);
    if ((t & 31) == 0) red[t >> 5] = s;
    __syncthreads();
    if (t < 8) {
        float r = red[t];
        #pragma unroll
        for (int o = 4; o > 0; o >>= 1) r += __shfl_xor_sync(0xffu, r, o);
        if (t == 0) red[0] = r;
    }
    __syncthreads();
    float val = v / sqrtf(red[0]) - center[t];
    g_xq[b * D_DIM + t] = val;
    g_qb[b * D_DIM + t] = __half_as_ushort(__float2half_rn(val));
}

__global__ void convert_kernel(const float* __restrict__ X, int N) {
    int w = (blockIdx.x * blockDim.x + threadIdx.x) >> 5;
    int lane = threadIdx.x & 31;
    if (w >= N) return;
    const float4* row = (const float4*)(X + (size_t)w * D_DIM);
    float4 v0 = row[lane * 2], v1 = row[lane * 2 + 1];
    float s = v0.x*v0.x + v0.y*v0.y + v0.z*v0.z + v0.w*v0.w
            + v1.x*v1.x + v1.y*v1.y + v1.z*v1.z + v1.w*v1.w;
    #pragma unroll
    for (int o = 16; o > 0; o >>= 1) s += __shfl_xor_sync(0xffffffffu, s, o);
    if (lane == 0) g_nx2[w] = s;
    uint4 o4;
    o4.x = __half_as_ushort(__float2half_rn(v0.x)) | ((unsigned)__half_as_ushort(__float2half_rn(v0.y)) << 16);
    o4.y = __half_as_ushort(__float2half_rn(v0.z)) | ((unsigned)__half_as_ushort(__float2half_rn(v0.w)) << 16);
    o4.z = __half_as_ushort(__float2half_rn(v1.x)) | ((unsigned)__half_as_ushort(__float2half_rn(v1.y)) << 16);
    o4.w = __half_as_ushort(__float2half_rn(v1.z)) | ((unsigned)__half_as_ushort(__float2half_rn(v1.w)) << 16);
    ((uint4*)(g_Xb + (size_t)w * D_DIM))[lane] = o4;
}

__global__ void init_kernel(int M) {
    int i = blockIdx.x * blockDim.x + threadIdx.x;
    if (i < M) { g_min[i] = ~0ull; g_cnum[i] = 0; }
}

// ---------------------------------------------------------------------------
// fp16 mma.sync GEMM (128x128x256), fp16 accumulate (2x HMMA rate),
// 2-stage cp.async, reg-resident argmin/margin epilogue
// ---------------------------------------------------------------------------
__device__ __forceinline__ void load_chunk(unsigned stage, int m0, int n0,
                                           int kc, int tid) {
    #pragma unroll
    for (int r = 0; r < 4; r++) {
        int idx = tid + 256 * r;
        int row = idx >> 3, g = idx & 7;
        cp16(stage + (row * ASTRIDE + g * 8) * 2,
             g_qb + (size_t)(m0 + row) * D_DIM + kc + g * 8);
        cp16(stage + 18432 + (row * ASTRIDE + g * 8) * 2,
             g_Xb + (size_t)(n0 + row) * D_DIM + kc + g * 8);
    }
}

__global__ __launch_bounds__(256, 2)
void gemm_kernel(int N, int M) {
    extern __shared__ char sm[];
    float* nxs = (float*)(sm + SM_NX);
    unsigned smu = smem_u32(sm);

    int tid = threadIdx.x;
    int w = tid >> 5, lane = tid & 31;
    int wm = w >> 1, wn = w & 1;   // warp tile m32 x n64
    int m0 = blockIdx.x * 128;
    int n0 = blockIdx.y * 128;

    if (tid < 128) {
        int gn = n0 + tid;
        nxs[tid] = (gn < N) ? g_nx2[gn] : 1e30f;
    }

    unsigned c[2][8][2];
    #pragma unroll
    for (int mi = 0; mi < 2; mi++)
        #pragma unroll
        for (int ni = 0; ni < 8; ni++) { c[mi][ni][0] = 0u; c[mi][ni][1] = 0u; }

    unsigned aoff = (unsigned)(((wm * 32 + (lane & 15)) * ASTRIDE + (lane >> 4) * 8) * 2);
    unsigned boff = (unsigned)(18432 +
        ((wn * 64 + ((lane >> 4) & 1) * 8 + (lane & 7)) * ASTRIDE + ((lane >> 3) & 1) * 8) * 2);

    load_chunk(smu, m0, n0, 0, tid);
    CP_COMMIT();

    #pragma unroll
    for (int kc = 0; kc < 4; kc++) {
        int buf = kc & 1;
        if (kc < 3) {
            load_chunk(smu + (buf ^ 1) * STAGE_BYTES, m0, n0, (kc + 1) * KC, tid);
            CP_COMMIT();
            CP_WAIT(1);
        } else {
            CP_WAIT(0);
        }
        __syncthreads();

        unsigned stage = smu + buf * STAGE_BYTES;
        unsigned Au = stage + aoff;
        unsigned Bu = stage + boff;
        #pragma unroll
        for (int ks = 0; ks < 4; ks++) {
            unsigned a[2][4];
            #pragma unroll
            for (int mi = 0; mi < 2; mi++)
                ldsm_x4(a[mi][0], a[mi][1], a[mi][2], a[mi][3],
                        Au + mi * (16 * ASTRIDE * 2) + ks * 32);
            unsigned b[4][4];
            #pragma unroll
            for (int p = 0; p < 4; p++)
                ldsm_x4(b[p][0], b[p][1], b[p][2], b[p][3],
                        Bu + p * (16 * ASTRIDE * 2) + ks * 32);
            #pragma unroll
            for (int mi = 0; mi < 2; mi++)
                #pragma unroll
                for (int p = 0; p < 4; p++) {
                    mma16816h(c[mi][2 * p + 0], a[mi], b[p][0], b[p][1]);
                    mma16816h(c[mi][2 * p + 1], a[mi], b[p][2], b[p][3]);
                }
        }
        __syncthreads();
    }

    // ---- register epilogue: per-row argmin + margin candidates ----
    int r = lane >> 2, qp = lane & 3;
    #pragma unroll
    for (int mi = 0; mi < 2; mi++) {
        #pragma unroll
        for (int h = 0; h < 2; h++) {
            int lrow = wm * 32 + mi * 16 + h * 8 + r;
            int q = m0 + lrow;
            unsigned long long kmin = ~0ull;
            #pragma unroll
            for (int ni = 0; ni < 8; ni++) {
                int lc = wn * 64 + ni * 8 + 2 * qp;
                float2 d = __half22float2(*(const __half2*)&c[mi][ni][h]);
                float s0 = fmaf(-2.f, d.x, nxs[lc]);
                float s1 = fmaf(-2.f, d.y, nxs[lc + 1]);
                unsigned long long k0 = ((unsigned long long)f2ord(s0) << 32) | (unsigned)(n0 + lc);
                unsigned long long k1 = ((unsigned long long)f2ord(s1) << 32) | (unsigned)(n0 + lc + 1);
                if (k0 < kmin) kmin = k0;
                if (k1 < kmin) kmin = k1;
            }
            unsigned long long o1 = __shfl_xor_sync(0xffffffffu, kmin, 1);
            if (o1 < kmin) kmin = o1;
            unsigned long long o2 = __shfl_xor_sync(0xffffffffu, kmin, 2);
            if (o2 < kmin) kmin = o2;

            float thr = 0.f;
            if (qp == 0 && q < M) {
                unsigned long long old = atomicMin(&g_min[q], kmin);
                unsigned long long cur = (old < kmin) ? old : kmin;
                thr = ord2f((unsigned)(cur >> 32)) + MARGIN;
            }
            thr = __shfl_sync(0xffffffffu, thr, lane & ~3);

            if (q < M) {
                #pragma unroll
                for (int ni = 0; ni < 8; ni++) {
                    int lc = wn * 64 + ni * 8 + 2 * qp;
                    float2 d = __half22float2(*(const __half2*)&c[mi][ni][h]);
                    float s0 = fmaf(-2.f, d.x, nxs[lc]);
                    float s1 = fmaf(-2.f, d.y, nxs[lc + 1]);
                    if (s0 < thr) {
                        int p = atomicAdd(&g_cnum[q], 1);
                        if (p < CAP) g_cand[q * CAP + p] = n0 + lc;
                    }
                    if (s1 < thr) {
                        int p = atomicAdd(&g_cnum[q], 1);
                        if (p < CAP) g_cand[q * CAP + p] = n0 + lc + 1;
                    }
                }
            }
        }
    }
}

// ---------------------------------------------------------------------------
__global__ void rescore_kernel(const float* __restrict__ X) {
    __shared__ float xq[D_DIM];
    __shared__ unsigned long long wmin[8];
    int q = blockIdx.x;
    int tid = threadIdx.x, w = tid >> 5, lane = tid & 31;
    xq[tid] = g_xq[q * D_DIM + tid];
    int cnum = min(g_cnum[q], CAP);
    __syncthreads();
    unsigned long long key = ~0ull;
    for (int c = w; c < cnum; c += 8) {
        int gn = g_cand[q * CAP + c];
        const float4* row = (const float4*)(X + (size_t)gn * D_DIM);
        const float4* xv = (const float4*)xq;
        float4 v0 = row[lane * 2], v1 = row[lane * 2 + 1];
        float4 a0 = xv[lane * 2], a1 = xv[lane * 2 + 1];
        float dp = v0.x*a0.x + v0.y*a0.y + v0.z*a0.z + v0.w*a0.w
                 + v1.x*a1.x + v1.y*a1.y + v1.z*a1.z + v1.w*a1.w;
        #pragma unroll
        for (int o = 16; o > 0; o >>= 1) dp += __shfl_xor_sync(0xffffffffu, dp, o);
        float s = g_nx2[gn] - 2.f * dp;
        unsigned long long k = ((unsigned long long)f2ord(s) << 32) | (unsigned)gn;
        if (k < key) key = k;
    }
    if (lane == 0) wmin[w] = key;
    __syncthreads();
    if (tid == 0) {
        unsigned long long best = wmin[0];
        #pragma unroll
        for (int i = 1; i < 8; i++) if (wmin[i] < best) best = wmin[i];
        g_min[q] = best;
    }
}

// ---------------------------------------------------------------------------
__global__ void finalize_kernel(const int* __restrict__ labels,
                                const int* __restrict__ tni,
                                const int* __restrict__ cali,
                                float* __restrict__ out,
                                int M, int ncali, int Kn) {
    __shared__ int scali[1024];
    __shared__ int wcnt[8][NBC];
    for (int i = threadIdx.x; i < ncali; i += blockDim.x) scali[i] = cali[i];
    int w = threadIdx.x >> 5, lane = threadIdx.x & 31;
    if (lane < NBC) wcnt[w][lane] = 0;
    __syncthreads();
    int b = blockIdx.x * 8 + w;
    if (b < M) {
        int closest = (int)(g_min[b] & 0xffffffffull);
        for (int e = lane; e < Kn; e += 32) {
            int idx = (e == 0) ? closest : tni[(size_t)closest * (Kn - 1) + (e - 1)];
            atomicAdd(&wcnt[w][labels[idx]], 1);
        }
        __syncwarp();
        int key = 0x7fffffff;
        if (lane < NBC) {
            int v = Kn - wcnt[w][lane];
            int lo = 0, hi = ncali;
            while (lo < hi) {
                int mid = (lo + hi) >> 1;
                if (scali[mid] < v) lo = mid + 1; else hi = mid;
            }
            key = lo * 16 + lane;
        }
        #pragma unroll
        for (int o = 16; o > 0; o >>= 1)
            key = min(key, __shfl_xor_sync(0xffffffffu, key, o));
        if (lane == 0) {
            int pred = key & 15, pos = key >> 4;
            float pmax = (float)(ncali - pos) / (float)ncali;
            #pragma unroll
            for (int c = 0; c < NBC; c++)
                out[b * NBC + c] = (c == pred) ? pmax : 0.f;
        }
    }
}

// ---------------------------------------------------------------------------
extern "C" void kernel_launch(void* const* d_in, const int* in_sizes, int n_in,
                              void* d_out, int out_size) {
    const float* x      = (const float*)d_in[0];
    const float* X      = (const float*)d_in[1];
    const float* center = (const float*)d_in[2];
    const int*   labels = (const int*)d_in[3];
    const int*   tni    = (const int*)d_in[4];
    const int*   cali   = (const int*)d_in[5];
    float*       out    = (float*)d_out;

    int d     = in_sizes[2];
    int M     = in_sizes[0] / d;
    int N     = in_sizes[3];
    int ncali = in_sizes[5];
    int Kn    = in_sizes[4] / N + 1;

    cudaFuncSetAttribute(gemm_kernel, cudaFuncAttributeMaxDynamicSharedMemorySize, SMEM_BYTES);

    prep_kernel<<<M, 256>>>(x, center, M);
    convert_kernel<<<(N + 7) / 8, 256>>>(X, N);
    init_kernel<<<(M + 255) / 256, 256>>>(M);

    dim3 grid((M + 127) / 128, (N + 127) / 128);
    gemm_kernel<<<grid, 256, SMEM_BYTES>>>(N, M);

    rescore_kernel<<<M, 256>>>(X);
    finalize_kernel<<<(M + 7) / 8, 256>>>(labels, tni, cali, out, M, ncali, Kn);
}

// round 12
// speedup vs baseline: 1.8875x; 1.0658x over previous
#include <cuda_runtime.h>
#include <cuda_fp16.h>
#include <cstdint>

#define D_DIM    256
#define NBC      10
#define MAX_M    1024
#define MAX_N    100000
#define MAX_NP   100096
#define CAP      2048
#define MARGIN   0.08f
#define KC       64
#define ASTRIDE  72      // fp16 elems per smem row (64 + 8 pad)

#define A_BYTES      36864                    // 256 x 72 x 2
#define B_BYTES      18432                    // 128 x 72 x 2
#define STAGE_BYTES  (A_BYTES + B_BYTES)      // 55296
#define SM_NX        (2 * STAGE_BYTES)        // 110592
#define SMEM_BYTES   (SM_NX + 512)            // 111104 -> 2 CTAs/SM

__device__ float              g_xq[MAX_M * D_DIM];
__device__ unsigned short     g_qb[MAX_M * D_DIM];          // fp16 bits
__device__ unsigned short     g_Xb[(size_t)MAX_NP * D_DIM]; // fp16 bits, pad rows 0
__device__ float              g_nx2[MAX_N];
__device__ unsigned long long g_min[MAX_M];
__device__ int                g_cnum[MAX_M];
__device__ int                g_cand[MAX_M * CAP];

__device__ __forceinline__ unsigned f2ord(float f) {
    unsigned u = __float_as_uint(f);
    return (u & 0x80000000u) ? ~u : (u | 0x80000000u);
}
__device__ __forceinline__ float ord2f(unsigned o) {
    return __uint_as_float((o & 0x80000000u) ? (o ^ 0x80000000u) : ~o);
}
__device__ __forceinline__ unsigned smem_u32(const void* p) {
    unsigned a;
    asm("{ .reg .u64 t; cvta.to.shared.u64 t, %1; cvt.u32.u64 %0, t; }" : "=r"(a) : "l"(p));
    return a;
}
__device__ __forceinline__ void cp16(unsigned dst, const void* src) {
    asm volatile("cp.async.cg.shared.global [%0], [%1], 16;" :: "r"(dst), "l"(src));
}
#define CP_COMMIT() asm volatile("cp.async.commit_group;" ::: "memory")
#define CP_WAIT(n)  asm volatile("cp.async.wait_group %0;" :: "n"(n) : "memory")

__device__ __forceinline__ void ldsm_x4(unsigned& r0, unsigned& r1, unsigned& r2, unsigned& r3, unsigned addr) {
    asm volatile("ldmatrix.sync.aligned.m8n8.x4.shared.b16 {%0,%1,%2,%3}, [%4];"
        : "=r"(r0), "=r"(r1), "=r"(r2), "=r"(r3) : "r"(addr));
}
__device__ __forceinline__ void mma16816h(unsigned* c, const unsigned* a, unsigned b0, unsigned b1) {
    asm volatile(
        "mma.sync.aligned.m16n8k16.row.col.f16.f16.f16.f16 "
        "{%0,%1}, {%2,%3,%4,%5}, {%6,%7}, {%0,%1};"
        : "+r"(c[0]), "+r"(c[1])
        : "r"(a[0]), "r"(a[1]), "r"(a[2]), "r"(a[3]), "r"(b0), "r"(b1));
}

// ---------------------------------------------------------------------------
__global__ void prep_kernel(const float* __restrict__ x,
                            const float* __restrict__ center, int M) {
    int b = blockIdx.x, t = threadIdx.x;
    float v = x[b * D_DIM + t];
    float s = v * v;
    __shared__ float red[8];
    #pragma unroll
    for (int o = 16; o > 0; o >>= 1) s += __shfl_xor_sync(0xffffffffu, s, o);
    if ((t & 31) == 0) red[t >> 5] = s;
    __syncthreads();
    if (t < 8) {
        float r = red[t];
        #pragma unroll
        for (int o = 4; o > 0; o >>= 1) r += __shfl_xor_sync(0xffu, r, o);
        if (t == 0) red[0] = r;
    }
    __syncthreads();
    float val = v / sqrtf(red[0]) - center[t];
    g_xq[b * D_DIM + t] = val;
    g_qb[b * D_DIM + t] = __half_as_ushort(__float2half_rn(val));
}

__global__ void convert_kernel(const float* __restrict__ X, int N) {
    int w = (blockIdx.x * blockDim.x + threadIdx.x) >> 5;
    int lane = threadIdx.x & 31;
    if (w >= N) return;
    const float4* row = (const float4*)(X + (size_t)w * D_DIM);
    float4 v0 = row[lane * 2], v1 = row[lane * 2 + 1];
    float s = v0.x*v0.x + v0.y*v0.y + v0.z*v0.z + v0.w*v0.w
            + v1.x*v1.x + v1.y*v1.y + v1.z*v1.z + v1.w*v1.w;
    #pragma unroll
    for (int o = 16; o > 0; o >>= 1) s += __shfl_xor_sync(0xffffffffu, s, o);
    if (lane == 0) g_nx2[w] = s;
    uint4 o4;
    o4.x = __half_as_ushort(__float2half_rn(v0.x)) | ((unsigned)__half_as_ushort(__float2half_rn(v0.y)) << 16);
    o4.y = __half_as_ushort(__float2half_rn(v0.z)) | ((unsigned)__half_as_ushort(__float2half_rn(v0.w)) << 16);
    o4.z = __half_as_ushort(__float2half_rn(v1.x)) | ((unsigned)__half_as_ushort(__float2half_rn(v1.y)) << 16);
    o4.w = __half_as_ushort(__float2half_rn(v1.z)) | ((unsigned)__half_as_ushort(__float2half_rn(v1.w)) << 16);
    ((uint4*)(g_Xb + (size_t)w * D_DIM))[lane] = o4;
}

__global__ void init_kernel(int M) {
    int i = blockIdx.x * blockDim.x + threadIdx.x;
    if (i < M) { g_min[i] = ~0ull; g_cnum[i] = 0; }
}

// ---------------------------------------------------------------------------
// fp16 mma.sync GEMM, CTA tile 256x128, warp tile m64xn64, fp16 accumulate,
// 2-stage cp.async, reg-resident argmin/margin epilogue
// ---------------------------------------------------------------------------
__device__ __forceinline__ void load_chunk(unsigned stage, int m0, int n0,
                                           int kc, int tid) {
    // A: 256 rows x 64 cols fp16 -> 2048 cp16 over 256 threads = 8 each
    #pragma unroll
    for (int r = 0; r < 8; r++) {
        int idx = tid + 256 * r;
        int row = idx >> 3, g = idx & 7;
        cp16(stage + (row * ASTRIDE + g * 8) * 2,
             g_qb + (size_t)(m0 + row) * D_DIM + kc + g * 8);
    }
    // B: 128 rows x 64 cols -> 1024 cp16 = 4 each
    #pragma unroll
    for (int r = 0; r < 4; r++) {
        int idx = tid + 256 * r;
        int row = idx >> 3, g = idx & 7;
        cp16(stage + A_BYTES + (row * ASTRIDE + g * 8) * 2,
             g_Xb + (size_t)(n0 + row) * D_DIM + kc + g * 8);
    }
}

__global__ __launch_bounds__(256, 2)
void gemm_kernel(int N, int M) {
    extern __shared__ char sm[];
    float* nxs = (float*)(sm + SM_NX);
    unsigned smu = smem_u32(sm);

    int tid = threadIdx.x;
    int w = tid >> 5, lane = tid & 31;
    int wm = w >> 1, wn = w & 1;   // 4 x 2 warp grid, warp tile m64 x n64
    int m0 = blockIdx.x * 256;
    int n0 = blockIdx.y * 128;

    if (tid < 128) {
        int gn = n0 + tid;
        nxs[tid] = (gn < N) ? g_nx2[gn] : 1e30f;
    }

    unsigned c[4][8][2];
    #pragma unroll
    for (int mi = 0; mi < 4; mi++)
        #pragma unroll
        for (int ni = 0; ni < 8; ni++) { c[mi][ni][0] = 0u; c[mi][ni][1] = 0u; }

    unsigned aoff = (unsigned)(((wm * 64 + (lane & 15)) * ASTRIDE + (lane >> 4) * 8) * 2);
    unsigned boff = (unsigned)(A_BYTES +
        ((wn * 64 + ((lane >> 4) & 1) * 8 + (lane & 7)) * ASTRIDE + ((lane >> 3) & 1) * 8) * 2);

    load_chunk(smu, m0, n0, 0, tid);
    CP_COMMIT();

    #pragma unroll
    for (int kc = 0; kc < 4; kc++) {
        int buf = kc & 1;
        if (kc < 3) {
            load_chunk(smu + (buf ^ 1) * STAGE_BYTES, m0, n0, (kc + 1) * KC, tid);
            CP_COMMIT();
            CP_WAIT(1);
        } else {
            CP_WAIT(0);
        }
        __syncthreads();

        unsigned stage = smu + buf * STAGE_BYTES;
        unsigned Au = stage + aoff;
        unsigned Bu = stage + boff;
        #pragma unroll
        for (int ks = 0; ks < 4; ks++) {
            unsigned a[4][4];
            #pragma unroll
            for (int mi = 0; mi < 4; mi++)
                ldsm_x4(a[mi][0], a[mi][1], a[mi][2], a[mi][3],
                        Au + mi * (16 * ASTRIDE * 2) + ks * 32);
            unsigned b[4][4];
            #pragma unroll
            for (int p = 0; p < 4; p++)
                ldsm_x4(b[p][0], b[p][1], b[p][2], b[p][3],
                        Bu + p * (16 * ASTRIDE * 2) + ks * 32);
            #pragma unroll
            for (int mi = 0; mi < 4; mi++)
                #pragma unroll
                for (int p = 0; p < 4; p++) {
                    mma16816h(c[mi][2 * p + 0], a[mi], b[p][0], b[p][1]);
                    mma16816h(c[mi][2 * p + 1], a[mi], b[p][2], b[p][3]);
                }
        }
        __syncthreads();
    }

    // ---- register epilogue: per-row argmin + margin candidates ----
    int r = lane >> 2, qp = lane & 3;
    #pragma unroll
    for (int mi = 0; mi < 4; mi++) {
        #pragma unroll
        for (int h = 0; h < 2; h++) {
            int lrow = wm * 64 + mi * 16 + h * 8 + r;
            int q = m0 + lrow;
            unsigned long long kmin = ~0ull;
            #pragma unroll
            for (int ni = 0; ni < 8; ni++) {
                int lc = wn * 64 + ni * 8 + 2 * qp;
                float2 d = __half22float2(*(const __half2*)&c[mi][ni][h]);
                float s0 = fmaf(-2.f, d.x, nxs[lc]);
                float s1 = fmaf(-2.f, d.y, nxs[lc + 1]);
                unsigned long long k0 = ((unsigned long long)f2ord(s0) << 32) | (unsigned)(n0 + lc);
                unsigned long long k1 = ((unsigned long long)f2ord(s1) << 32) | (unsigned)(n0 + lc + 1);
                if (k0 < kmin) kmin = k0;
                if (k1 < kmin) kmin = k1;
            }
            unsigned long long o1 = __shfl_xor_sync(0xffffffffu, kmin, 1);
            if (o1 < kmin) kmin = o1;
            unsigned long long o2 = __shfl_xor_sync(0xffffffffu, kmin, 2);
            if (o2 < kmin) kmin = o2;

            float thr = 0.f;
            if (qp == 0 && q < M) {
                unsigned long long old = atomicMin(&g_min[q], kmin);
                unsigned long long cur = (old < kmin) ? old : kmin;
                thr = ord2f((unsigned)(cur >> 32)) + MARGIN;
            }
            thr = __shfl_sync(0xffffffffu, thr, lane & ~3);

            if (q < M) {
                #pragma unroll
                for (int ni = 0; ni < 8; ni++) {
                    int lc = wn * 64 + ni * 8 + 2 * qp;
                    float2 d = __half22float2(*(const __half2*)&c[mi][ni][h]);
                    float s0 = fmaf(-2.f, d.x, nxs[lc]);
                    float s1 = fmaf(-2.f, d.y, nxs[lc + 1]);
                    if (s0 < thr) {
                        int p = atomicAdd(&g_cnum[q], 1);
                        if (p < CAP) g_cand[q * CAP + p] = n0 + lc;
                    }
                    if (s1 < thr) {
                        int p = atomicAdd(&g_cnum[q], 1);
                        if (p < CAP) g_cand[q * CAP + p] = n0 + lc + 1;
                    }
                }
            }
        }
    }
}

// ---------------------------------------------------------------------------
__global__ void rescore_kernel(const float* __restrict__ X) {
    __shared__ float xq[D_DIM];
    __shared__ unsigned long long wmin[8];
    int q = blockIdx.x;
    int tid = threadIdx.x, w = tid >> 5, lane = tid & 31;
    xq[tid] = g_xq[q * D_DIM + tid];
    int cnum = min(g_cnum[q], CAP);
    __syncthreads();
    unsigned long long key = ~0ull;
    for (int c = w; c < cnum; c += 8) {
        int gn = g_cand[q * CAP + c];
        const float4* row = (const float4*)(X + (size_t)gn * D_DIM);
        const float4* xv = (const float4*)xq;
        float4 v0 = row[lane * 2], v1 = row[lane * 2 + 1];
        float4 a0 = xv[lane * 2], a1 = xv[lane * 2 + 1];
        float dp = v0.x*a0.x + v0.y*a0.y + v0.z*a0.z + v0.w*a0.w
                 + v1.x*a1.x + v1.y*a1.y + v1.z*a1.z + v1.w*a1.w;
        #pragma unroll
        for (int o = 16; o > 0; o >>= 1) dp += __shfl_xor_sync(0xffffffffu, dp, o);
        float s = g_nx2[gn] - 2.f * dp;
        unsigned long long k = ((unsigned long long)f2ord(s) << 32) | (unsigned)gn;
        if (k < key) key = k;
    }
    if (lane == 0) wmin[w] = key;
    __syncthreads();
    if (tid == 0) {
        unsigned long long best = wmin[0];
        #pragma unroll
        for (int i = 1; i < 8; i++) if (wmin[i] < best) best = wmin[i];
        g_min[q] = best;
    }
}

// ---------------------------------------------------------------------------
__global__ void finalize_kernel(const int* __restrict__ labels,
                                const int* __restrict__ tni,
                                const int* __restrict__ cali,
                                float* __restrict__ out,
                                int M, int ncali, int Kn) {
    __shared__ int scali[1024];
    __shared__ int wcnt[8][NBC];
    for (int i = threadIdx.x; i < ncali; i += blockDim.x) scali[i] = cali[i];
    int w = threadIdx.x >> 5, lane = threadIdx.x & 31;
    if (lane < NBC) wcnt[w][lane] = 0;
    __syncthreads();
    int b = blockIdx.x * 8 + w;
    if (b < M) {
        int closest = (int)(g_min[b] & 0xffffffffull);
        for (int e = lane; e < Kn; e += 32) {
            int idx = (e == 0) ? closest : tni[(size_t)closest * (Kn - 1) + (e - 1)];
            atomicAdd(&wcnt[w][labels[idx]], 1);
        }
        __syncwarp();
        int key = 0x7fffffff;
        if (lane < NBC) {
            int v = Kn - wcnt[w][lane];
            int lo = 0, hi = ncali;
            while (lo < hi) {
                int mid = (lo + hi) >> 1;
                if (scali[mid] < v) lo = mid + 1; else hi = mid;
            }
            key = lo * 16 + lane;
        }
        #pragma unroll
        for (int o = 16; o > 0; o >>= 1)
            key = min(key, __shfl_xor_sync(0xffffffffu, key, o));
        if (lane == 0) {
            int pred = key & 15, pos = key >> 4;
            float pmax = (float)(ncali - pos) / (float)ncali;
            #pragma unroll
            for (int c = 0; c < NBC; c++)
                out[b * NBC + c] = (c == pred) ? pmax : 0.f;
        }
    }
}

// ---------------------------------------------------------------------------
extern "C" void kernel_launch(void* const* d_in, const int* in_sizes, int n_in,
                              void* d_out, int out_size) {
    const float* x      = (const float*)d_in[0];
    const float* X      = (const float*)d_in[1];
    const float* center = (const float*)d_in[2];
    const int*   labels = (const int*)d_in[3];
    const int*   tni    = (const int*)d_in[4];
    const int*   cali   = (const int*)d_in[5];
    float*       out    = (float*)d_out;

    int d     = in_sizes[2];
    int M     = in_sizes[0] / d;
    int N     = in_sizes[3];
    int ncali = in_sizes[5];
    int Kn    = in_sizes[4] / N + 1;

    cudaFuncSetAttribute(gemm_kernel, cudaFuncAttributeMaxDynamicSharedMemorySize, SMEM_BYTES);

    prep_kernel<<<M, 256>>>(x, center, M);
    convert_kernel<<<(N + 7) / 8, 256>>>(X, N);
    init_kernel<<<(M + 255) / 256, 256>>>(M);

    dim3 grid((M + 255) / 256, (N + 127) / 128);
    gemm_kernel<<<grid, 256, SMEM_BYTES>>>(N, M);

    rescore_kernel<<<M, 256>>>(X);
    finalize_kernel<<<(M + 7) / 8, 256>>>(labels, tni, cali, out, M, ncali, Kn);
}